// round 10
// baseline (speedup 1.0000x reference)
#include <cuda_runtime.h>
#include <math.h>

// Problem constants
#define NN 16
#define CC 256
#define HH 96
#define WW 96
#define HW (HH*WW)          // 9216
#define RED 16
#define HID (CC/RED)        // 16
#define KK 3
#define DYN (CC*KK*KK)      // 2304
#define EPS 1e-5f

#define NPC 4               // images per chunk (37.8 MB of x -> L2 resident)
#define NCPC (NPC*CC)       // 1024 (n,c) pairs per chunk
#define NCHUNK (NN/NPC)     // 4

// Scratch (allocation-free rule: __device__ globals)
__device__ float d_g[NN*CC];       // sigmoid gate per (n,c)
__device__ float d_gap[NN*CC];     // g * mean  (== mean of srm)
__device__ float d_hid[NN*HID];    // MLP layer-1 activations
__device__ int   d_cnt = 0;        // last-block counter (self-resetting)

// ---------------------------------------------------------------------------
// Kernel 1 (per chunk): per-(n,c) mean/std -> gate g, gap = g*mean.
// The LAST block of the chunk also computes MLP layer-1 (hid) for the
// chunk's NPC images (atomic-counter pattern; counter resets itself so
// every kernel_launch call sees the same initial state).
// ---------------------------------------------------------------------------
__global__ void __launch_bounds__(256) stats_kernel(const float* __restrict__ x,
                                                    const float* __restrict__ cfc,
                                                    const float* __restrict__ w1,
                                                    const float* __restrict__ b1,
                                                    int nc0) {
    int nc = nc0 + blockIdx.x;
    const float4* xp = (const float4*)(x + (size_t)nc * HW);

    float s = 0.f, s2 = 0.f;
    #pragma unroll
    for (int i = threadIdx.x; i < HW/4; i += 256) {
        float4 v = xp[i];
        s  += v.x + v.y + v.z + v.w;
        s2 += v.x*v.x + v.y*v.y + v.z*v.z + v.w*v.w;
    }
    #pragma unroll
    for (int o = 16; o; o >>= 1) {
        s  += __shfl_xor_sync(0xffffffffu, s,  o);
        s2 += __shfl_xor_sync(0xffffffffu, s2, o);
    }
    __shared__ float ss[8], ss2[8];
    __shared__ int islast;
    int w = threadIdx.x >> 5;
    if ((threadIdx.x & 31) == 0) { ss[w] = s; ss2[w] = s2; }
    __syncthreads();
    if (threadIdx.x == 0) {
        s = 0.f; s2 = 0.f;
        #pragma unroll
        for (int i = 0; i < 8; i++) { s += ss[i]; s2 += ss2[i]; }
        float mean = s * (1.f / (float)HW);
        float var  = (s2 - s * mean) * (1.f / (float)(HW - 1));  // unbiased
        float stdv = sqrtf(var + EPS);
        int c = nc & (CC - 1);
        float z = mean * cfc[2*c] + stdv * cfc[2*c + 1];
        float g = 1.f / (1.f + __expf(-z));
        d_g[nc]   = g;
        d_gap[nc] = g * mean;
        __threadfence();                       // publish g/gap before counting
        int old = atomicAdd(&d_cnt, 1);
        islast = (old == NCPC - 1);
        if (islast) d_cnt = 0;                 // restore for next chunk/call
    }
    __syncthreads();
    if (!islast) return;

    // --- last block: hid[r] = relu(b1[r] + sum_c gap[c]*w1[r,c]) for NPC images
    __threadfence();
    int n0  = nc0 / CC;
    int t   = threadIdx.x;
    int img = t >> 6;            // 0..3
    int r   = (t >> 2) & 15;     // 0..15
    int p   = t & 3;             // 0..3
    const float* gp = d_gap + (size_t)(n0 + img) * CC;
    const float* wr = w1 + r * CC;
    float acc = 0.f;
    #pragma unroll
    for (int c = p; c < CC; c += 4) acc += gp[c] * wr[c];
    acc += __shfl_xor_sync(0xffffffffu, acc, 1);
    acc += __shfl_xor_sync(0xffffffffu, acc, 2);
    if (p == 0) d_hid[(n0 + img)*HID + r] = fmaxf(acc + b1[r], 0.f);
}

// ---------------------------------------------------------------------------
// Kernel 2 (per chunk): depthwise 3x3 conv, 2 half-tiles per (n,c).
// x re-read is an L2 HIT (chunk just streamed by stats). Threads 0..8 of
// each block generate their 9 filter taps from hid/w2/b2 (g folded in).
// x loads __ldcs (dead after use), out stores __stcs (streaming).
// ---------------------------------------------------------------------------
#define SW 98
#define TR 50            // tile rows (48 + 2 halo)
#define HALF 48
__global__ void __launch_bounds__(192, 8) conv_kernel(const float* __restrict__ x,
                                                      float* __restrict__ out,
                                                      const float* __restrict__ w2,
                                                      const float* __restrict__ b2,
                                                      int nc0) {
    __shared__ float tile[TR*SW];   // 19600 B
    __shared__ float fs[9];

    int bid  = blockIdx.x;
    int nc   = nc0 + (bid >> 1);
    int half = bid & 1;
    int h0   = half * HALF;
    int t    = threadIdx.x;          // 0..191
    int n    = nc >> 8;              // / CC
    int c    = nc & (CC - 1);

    // generate this block's 9 taps: filt[k] = g * (b2[c*9+k] + hid . w2_row)
    if (t < 9) {
        int o = c * 9 + t;
        const float* wr  = w2 + o * HID;
        const float* hid = d_hid + n * HID;
        float acc = b2[o];
        #pragma unroll
        for (int r = 0; r < HID; r++) acc += hid[r] * wr[r];
        fs[t] = acc * d_g[nc];
    }

    // zero left/right halo columns: 50 rows x 2 = 100 cells
    if (t < 2*TR) {
        int row = t >> 1;
        tile[row*SW + ((t & 1) ? 97 : 0)] = 0.f;
    }

    // load interior: 50 rows x 24 float4-segments = 1200 units
    const float4* xp = (const float4*)(x + (size_t)nc * HW);
    for (int i = t; i < TR*24; i += 192) {
        int row = i / 24;
        int seg = i - row * 24;
        int gr  = h0 - 1 + row;
        float4 v = make_float4(0.f, 0.f, 0.f, 0.f);
        if (gr >= 0 && gr < HH) v = __ldcs(&xp[gr * (WW/4) + seg]);
        float* dst = &tile[row*SW + seg*4 + 1];
        dst[0] = v.x; dst[1] = v.y; dst[2] = v.z; dst[3] = v.w;
    }
    __syncthreads();

    float f0 = fs[0], f1 = fs[1], f2 = fs[2];
    float f3 = fs[3], f4 = fs[4], f5 = fs[5];
    float f6 = fs[6], f7 = fs[7], f8 = fs[8];

    int g   = t % 24;                // column group: output cols [4g, 4g+4)
    int y   = t / 24;                // row strip: local rows [6y, 6y+6)
    int lr0 = y * 6;

    const float* base = &tile[lr0*SW + 4*g];
    float4* op = (float4*)(out + (size_t)nc * HW + (h0 + lr0) * WW + 4*g);

    float a0,a1,a2,a3,a4,a5, b0,b1,b2r,b3,b4,b5;
    a0=base[0]; a1=base[1]; a2=base[2]; a3=base[3]; a4=base[4]; a5=base[5]; base += SW;
    b0=base[0]; b1=base[1]; b2r=base[2]; b3=base[3]; b4=base[4]; b5=base[5];

    #pragma unroll
    for (int i = 0; i < 6; i++) {
        base += SW;
        float c0=base[0], c1=base[1], c2=base[2], c3=base[3], c4=base[4], c5=base[5];
        float4 o4;
        o4.x = f0*a0+f1*a1+f2*a2 + f3*b0+f4*b1+f5*b2r + f6*c0+f7*c1+f8*c2;
        o4.y = f0*a1+f1*a2+f2*a3 + f3*b1+f4*b2r+f5*b3 + f6*c1+f7*c2+f8*c3;
        o4.z = f0*a2+f1*a3+f2*a4 + f3*b2r+f4*b3+f5*b4 + f6*c2+f7*c3+f8*c4;
        o4.w = f0*a3+f1*a4+f2*a5 + f3*b3+f4*b4+f5*b5 + f6*c3+f7*c4+f8*c5;
        __stcs(&op[i * (WW/4)], o4);
        a0=b0; a1=b1; a2=b2r; a3=b3; a4=b4; a5=b5;
        b0=c0; b1=c1; b2r=c2; b3=c3; b4=c4; b5=c5;
    }
}

// ---------------------------------------------------------------------------
extern "C" void kernel_launch(void* const* d_in, const int* in_sizes, int n_in,
                              void* d_out, int out_size) {
    const float* x   = (const float*)d_in[0];
    const float* cfc = (const float*)d_in[1];
    const float* w1  = (const float*)d_in[2];
    const float* b1  = (const float*)d_in[3];
    const float* w2  = (const float*)d_in[4];
    const float* b2  = (const float*)d_in[5];
    float* out = (float*)d_out;

    for (int chunk = 0; chunk < NCHUNK; chunk++) {
        int nc0 = chunk * NCPC;
        stats_kernel<<<NCPC, 256>>>(x, cfc, w1, b1, nc0);
        conv_kernel<<<NCPC*2, 192>>>(x, out, w2, b2, nc0);
    }
}